// round 2
// baseline (speedup 1.0000x reference)
#include <cuda_runtime.h>

#define N_NODES 255
#define NNZ_E   2550
#define BATCH   512
#define M_ROWS  (BATCH * N_NODES)   // 130560 (divisible by 128)
#define MAXD    400

// ---------------- device scratch (no allocations allowed) ----------------
__device__ float g_bufA[M_ROWS * MAXD];
__device__ float g_bufB[M_ROWS * MAXD];
__device__ int   g_rowptr[2][N_NODES + 1];
__device__ int   g_cols[2][NNZ_E];
__device__ float g_vals[2][NNZ_E];
__device__ float g_rowsum[2][N_NODES];

// ---------------- deterministic COO -> CSR build (1 block per matrix) ----
__global__ void build_csr_kernel(const int* __restrict__ sm_idx, const float* __restrict__ sm_val,
                                 const int* __restrict__ sp_idx, const float* __restrict__ sp_val) {
    __shared__ int   srow[NNZ_E];
    __shared__ float sval[NNZ_E];
    __shared__ int   rptr[N_NODES + 1];
    __shared__ int   cnt[N_NODES];
    const int mat = blockIdx.x;
    const int*   idx = mat ? sp_idx : sm_idx;
    const float* val = mat ? sp_val : sm_val;
    const int t = threadIdx.x;

    for (int e = t; e < NNZ_E; e += blockDim.x) { srow[e] = idx[2 * e]; sval[e] = val[e]; }
    for (int i = t; i < N_NODES; i += blockDim.x) cnt[i] = 0;
    __syncthreads();
    for (int e = t; e < NNZ_E; e += blockDim.x) atomicAdd(&cnt[srow[e]], 1);
    __syncthreads();
    if (t == 0) {
        int s = 0;
        for (int i = 0; i < N_NODES; i++) { rptr[i] = s; s += cnt[i]; }
        rptr[N_NODES] = s;
    }
    __syncthreads();
    // rank within row by original edge order -> fully deterministic CSR
    for (int e = t; e < NNZ_E; e += blockDim.x) {
        const int r = srow[e];
        int rank = 0;
        for (int e2 = 0; e2 < e; e2++) rank += (srow[e2] == r) ? 1 : 0;
        const int slot = rptr[r] + rank;
        g_cols[mat][slot] = idx[2 * e + 1];
        g_vals[mat][slot] = sval[e];
    }
    for (int i = t; i <= N_NODES; i += blockDim.x) g_rowptr[mat][i] = rptr[i];
    // deterministic per-row sums (serial per row, edge order)
    for (int i = t; i < N_NODES; i += blockDim.x) {
        float s = 0.f;
        for (int e = 0; e < NNZ_E; e++)
            if (srow[e] == i) s += sval[e];
        g_rowsum[mat][i] = s;
    }
}

// ---------------- SpMM, feature dim = 2 (thread per (b,i)) ---------------
__global__ void spmm_d2_kernel(int mat, const float* __restrict__ X,
                               float* __restrict__ out, int relu) {
    const int t = blockIdx.x * blockDim.x + threadIdx.x;
    if (t >= M_ROWS) return;
    const int b = t / N_NODES;
    const int i = t - b * N_NODES;
    const int p0 = g_rowptr[mat][i], p1 = g_rowptr[mat][i + 1];
    const float2* Xb = reinterpret_cast<const float2*>(X) + (size_t)b * N_NODES;
    float a0 = 0.f, a1 = 0.f;
    for (int e = p0; e < p1; e++) {
        const float v = g_vals[mat][e];
        const float2 x = Xb[g_cols[mat][e]];
        a0 = fmaf(v, x.x, a0);
        a1 = fmaf(v, x.y, a1);
    }
    if (relu) { a0 = fmaxf(a0, 0.f); a1 = fmaxf(a1, 0.f); }
    reinterpret_cast<float2*>(out)[t] = make_float2(a0, a1);
}

// ---------------- SpMM, generic d (d % 4 == 0), block per (i, b) ---------
__global__ void spmm_kernel(int mat, const float* __restrict__ Z,
                            float* __restrict__ out, int d, int relu) {
    const int i = blockIdx.x, b = blockIdx.y;
    const int p0 = g_rowptr[mat][i], p1 = g_rowptr[mat][i + 1];
    const float* Zb = Z + (size_t)b * N_NODES * d;
    float* ob = out + ((size_t)b * N_NODES + i) * d;
    const int d4 = d >> 2;
    for (int q = threadIdx.x; q < d4; q += blockDim.x) {
        float4 acc = make_float4(0.f, 0.f, 0.f, 0.f);
        for (int e = p0; e < p1; e++) {
            const float v = g_vals[mat][e];
            const float4 z = *reinterpret_cast<const float4*>(Zb + g_cols[mat][e] * d + q * 4);
            acc.x = fmaf(v, z.x, acc.x);
            acc.y = fmaf(v, z.y, acc.y);
            acc.z = fmaf(v, z.z, acc.z);
            acc.w = fmaf(v, z.w, acc.w);
        }
        if (relu) {
            acc.x = fmaxf(acc.x, 0.f); acc.y = fmaxf(acc.y, 0.f);
            acc.z = fmaxf(acc.z, 0.f); acc.w = fmaxf(acc.w, 0.f);
        }
        *reinterpret_cast<float4*>(ob + q * 4) = acc;
    }
}

// ---------------- main GEMM: C = act(A @ W + scale*bias) -----------------
// MODE 0: C = A@W + bias                      (SpMM follows, ReLU there)
// MODE 1: C = relu(A@W + rowsum[m%255]*bias)  (SpMM already applied to A)
// fp32 with packed fma.rn.f32x2 (sm_103a: 3-reg scalar FFMA is half-rate)
#define BM 128
#define BN 128
#define BK 8

typedef unsigned long long u64;

__device__ __forceinline__ void ffma2(u64& d, u64 a, u64 b) {
    asm("fma.rn.f32x2 %0, %1, %2, %0;" : "+l"(d) : "l"(a), "l"(b));
}

template <int MODE>
__global__ __launch_bounds__(256, 2)
void gemm_kernel(const float* __restrict__ A, const float* __restrict__ Wt,
                 const float* __restrict__ bias, int mat,
                 float* __restrict__ C, int K, int N) {
    __shared__ float As2[BK][2 * BM];  // A values duplicated into f32x2 lane pairs
    __shared__ float Bs[BK][BN];

    const int tid = threadIdx.x;
    const int mBase = blockIdx.x * BM;
    const int nBase = blockIdx.y * BN;
    const int tr = (tid >> 4) << 3;  // 0..120
    const int tc = (tid & 15) << 3;  // 0..120

    u64 acc[8][4];
#pragma unroll
    for (int i = 0; i < 8; i++)
#pragma unroll
        for (int j = 0; j < 4; j++) acc[i][j] = 0ull;

    const int arow = tid >> 1;
    const int akoff = (tid & 1) * 4;
    const int brow = tid >> 5;        // 0..7
    const int bcol = (tid & 31) * 4;  // 0..124
    const float* Aptr = A + (size_t)(mBase + arow) * K;
    const bool kvec = ((K & 3) == 0);

    for (int k0 = 0; k0 < K; k0 += BK) {
        // stage loads
        float4 av;
        if (kvec) {
            av = (k0 + akoff < K) ? *reinterpret_cast<const float4*>(Aptr + k0 + akoff)
                                  : make_float4(0.f, 0.f, 0.f, 0.f);
        } else {
            av.x = (k0 + akoff + 0 < K) ? Aptr[k0 + akoff + 0] : 0.f;
            av.y = (k0 + akoff + 1 < K) ? Aptr[k0 + akoff + 1] : 0.f;
            av.z = (k0 + akoff + 2 < K) ? Aptr[k0 + akoff + 2] : 0.f;
            av.w = (k0 + akoff + 3 < K) ? Aptr[k0 + akoff + 3] : 0.f;
        }
        float4 bv = make_float4(0.f, 0.f, 0.f, 0.f);
        if (k0 + brow < K && nBase + bcol < N)
            bv = *reinterpret_cast<const float4*>(Wt + (size_t)(k0 + brow) * N + nBase + bcol);

        __syncthreads();  // previous iteration's smem reads done
        As2[akoff + 0][2 * arow] = av.x; As2[akoff + 0][2 * arow + 1] = av.x;
        As2[akoff + 1][2 * arow] = av.y; As2[akoff + 1][2 * arow + 1] = av.y;
        As2[akoff + 2][2 * arow] = av.z; As2[akoff + 2][2 * arow + 1] = av.z;
        As2[akoff + 3][2 * arow] = av.w; As2[akoff + 3][2 * arow + 1] = av.w;
        *reinterpret_cast<float4*>(&Bs[brow][bcol]) = bv;
        __syncthreads();

#pragma unroll
        for (int kk = 0; kk < BK; kk++) {
            u64 ap[8], bp[4];
#pragma unroll
            for (int i = 0; i < 8; i++)
                ap[i] = *reinterpret_cast<const u64*>(&As2[kk][2 * (tr + i)]);
#pragma unroll
            for (int j = 0; j < 4; j++)
                bp[j] = *reinterpret_cast<const u64*>(&Bs[kk][tc + 2 * j]);
#pragma unroll
            for (int i = 0; i < 8; i++)
#pragma unroll
                for (int j = 0; j < 4; j++) ffma2(acc[i][j], ap[i], bp[j]);
        }
    }

    // epilogue
    float bcols[8];
#pragma unroll
    for (int j = 0; j < 8; j++) {
        const int n = nBase + tc + j;
        bcols[j] = (n < N) ? bias[n] : 0.f;
    }
#pragma unroll
    for (int i = 0; i < 8; i++) {
        const int m = mBase + tr + i;
        float sc = 1.f;
        if (MODE == 1) sc = g_rowsum[mat][m % N_NODES];
        float outv[8];
#pragma unroll
        for (int j = 0; j < 4; j++) {
            const float2 p = *reinterpret_cast<float2*>(&acc[i][j]);
            outv[2 * j]     = p.x + bcols[2 * j] * sc;
            outv[2 * j + 1] = p.y + bcols[2 * j + 1] * sc;
        }
        if (MODE == 1) {
#pragma unroll
            for (int j = 0; j < 8; j++) outv[j] = fmaxf(outv[j], 0.f);
        }
        float* crow = C + (size_t)m * N + nBase + tc;
#pragma unroll
        for (int j4 = 0; j4 < 2; j4++) {
            const int n = nBase + tc + j4 * 4;
            if (n < N)  // n%4==0 and N%4==0 -> whole float4 valid
                *reinterpret_cast<float4*>(crow + j4 * 4) =
                    make_float4(outv[4 * j4], outv[4 * j4 + 1], outv[4 * j4 + 2], outv[4 * j4 + 3]);
        }
    }
}

// ---------------- thin GEMM for N=2 (dec2): warp per row -----------------
__global__ void gemm_thin_kernel(const float* __restrict__ X, const float* __restrict__ Wt,
                                 const float* __restrict__ bias, float* __restrict__ out, int K) {
    __shared__ float Ws[2 * MAXD];
    for (int i = threadIdx.x; i < 2 * K; i += blockDim.x) Ws[i] = Wt[i];
    __syncthreads();
    const int warp = threadIdx.x >> 5, lane = threadIdx.x & 31;
    const int row = blockIdx.x * 8 + warp;
    if (row >= M_ROWS) return;
    const float* x = X + (size_t)row * K;
    float a0 = 0.f, a1 = 0.f;
    for (int k = lane; k < K; k += 32) {
        const float xv = x[k];
        a0 = fmaf(xv, Ws[2 * k], a0);
        a1 = fmaf(xv, Ws[2 * k + 1], a1);
    }
#pragma unroll
    for (int off = 16; off; off >>= 1) {
        a0 += __shfl_down_sync(0xffffffffu, a0, off);
        a1 += __shfl_down_sync(0xffffffffu, a1, off);
    }
    if (lane == 0) {
        out[2 * row]     = a0 + bias[0];
        out[2 * row + 1] = a1 + bias[1];
    }
}

// ---------------- launch -------------------------------------------------
static inline int spmm_threads(int d) {
    int t = ((d >> 2) + 31) & ~31;
    if (t < 32) t = 32;
    if (t > 128) t = 128;
    return t;
}

extern "C" void kernel_launch(void* const* d_in, const int* in_sizes, int n_in,
                              void* d_out, int out_size) {
    const float* H   = (const float*)d_in[0];
    const float* smv = (const float*)d_in[1];
    const float* spv = (const float*)d_in[2];
    const float* W[6];
    const float* bb[6];
    for (int i = 0; i < 6; i++) {
        W[i]  = (const float*)d_in[3 + 2 * i];
        bb[i] = (const float*)d_in[4 + 2 * i];
    }
    const int* smi = (const int*)d_in[15];
    const int* spi = (const int*)d_in[16];
    float* out = (float*)d_out;

    float *bufA, *bufB;
    cudaGetSymbolAddress((void**)&bufA, g_bufA);
    cudaGetSymbolAddress((void**)&bufB, g_bufB);

    build_csr_kernel<<<2, 256>>>(smi, smv, spi, spv);

    const int tpb = 256;
    const int mblk = M_ROWS / BM;  // 1020

    // enc0 (2->400): SpMM-first on d=2, fused bias*rowsum + ReLU in GEMM
    spmm_d2_kernel<<<(M_ROWS + tpb - 1) / tpb, tpb>>>(0, H, bufA, 0);
    gemm_kernel<1><<<dim3(mblk, 4), 256>>>(bufA, W[0], bb[0], 0, bufB, 2, 400);

    // enc1 (400->300): GEMM+bias, then SpMM+ReLU on d=300
    gemm_kernel<0><<<dim3(mblk, 3), 256>>>(bufB, W[1], bb[1], 0, bufA, 400, 300);
    spmm_kernel<<<dim3(N_NODES, BATCH), spmm_threads(300)>>>(0, bufA, bufB, 300, 1);

    // enc2 (300->100): GEMM+bias, then SpMM+ReLU on d=100
    gemm_kernel<0><<<dim3(mblk, 1), 256>>>(bufB, W[2], bb[2], 0, bufA, 300, 100);
    spmm_kernel<<<dim3(N_NODES, BATCH), spmm_threads(100)>>>(0, bufA, bufB, 100, 1);

    // dec0 (100->300): SpMM-first (sp) on d=100, fused epilogue GEMM
    spmm_kernel<<<dim3(N_NODES, BATCH), spmm_threads(100)>>>(1, bufB, bufA, 100, 0);
    gemm_kernel<1><<<dim3(mblk, 3), 256>>>(bufA, W[3], bb[3], 1, bufB, 100, 300);

    // dec1 (300->400): SpMM-first (sp) on d=300, fused epilogue GEMM
    spmm_kernel<<<dim3(N_NODES, BATCH), spmm_threads(300)>>>(1, bufB, bufA, 300, 0);
    gemm_kernel<1><<<dim3(mblk, 4), 256>>>(bufA, W[4], bb[4], 1, bufB, 300, 400);

    // dec2 (400->2): thin GEMM+bias, then SpMM+ReLU on d=2 into d_out
    gemm_thin_kernel<<<M_ROWS / 8, 256>>>(bufB, W[5], bb[5], bufA, 400);
    spmm_d2_kernel<<<(M_ROWS + tpb - 1) / tpb, tpb>>>(1, bufA, out, 1);
}